// round 5
// baseline (speedup 1.0000x reference)
#include <cuda_runtime.h>
#include <math.h>

// ---------------- scratch (no allocations allowed) ----------------
__device__ __align__(16) float g_sum[2][256];    // pass-1: sum(x)
__device__ __align__(16) float g_sumax[2][256];  // pass-2: sum(att*x)
__device__ __align__(16) float g_outv[2][256];   // pass-3: graph embedding (one head)
__device__ __align__(16) float g_h1[2][256];
__device__ __align__(16) float g_h2[2][256];
__device__ float g_wacc[16];                      // w_term + v_term accumulator

__device__ __forceinline__ float sigf_fast(float z) { return 1.0f / (1.0f + __expf(-z)); }

static const int PGRID = 1184;  // 148 SMs * 8 blocks of 256 thr

// ---------------- zero accumulators ----------------
__global__ void k_zero() {
    int t = threadIdx.x;
    g_sum[0][t] = 0.f;  g_sum[1][t] = 0.f;
    g_sumax[0][t] = 0.f; g_sumax[1][t] = 0.f;
    g_outv[0][t] = 0.f;  g_outv[1][t] = 0.f;
    if (t < 16) g_wacc[t] = 0.f;
}

// ---------------- pass 1: column sum of x ----------------
__global__ void __launch_bounds__(256) k_sum(const float4* __restrict__ x, int nrows, int g) {
    __shared__ float bacc[256];
    int t = threadIdx.x;
    bacc[t] = 0.f;
    __syncthreads();
    int lane = t & 31;
    int gw = (blockIdx.x << 3) + (t >> 5);
    int nW = gridDim.x << 3;
    float4 a0 = make_float4(0.f,0.f,0.f,0.f), a1 = make_float4(0.f,0.f,0.f,0.f);
    for (int r = gw; r < nrows; r += nW) {
        const float4* row = x + (size_t)r * 64;
        float4 v0 = row[lane];
        float4 v1 = row[lane + 32];
        a0.x += v0.x; a0.y += v0.y; a0.z += v0.z; a0.w += v0.w;
        a1.x += v1.x; a1.y += v1.y; a1.z += v1.z; a1.w += v1.w;
    }
    int c = lane * 4;
    atomicAdd(&bacc[c + 0], a0.x); atomicAdd(&bacc[c + 1], a0.y);
    atomicAdd(&bacc[c + 2], a0.z); atomicAdd(&bacc[c + 3], a0.w);
    atomicAdd(&bacc[128 + c + 0], a1.x); atomicAdd(&bacc[128 + c + 1], a1.y);
    atomicAdd(&bacc[128 + c + 2], a1.z); atomicAdd(&bacc[128 + c + 3], a1.w);
    __syncthreads();
    atomicAdd(&g_sum[g][t], bacc[t]);
}

// ---------------- tiny matvec: h = tanh((src/N) @ W0) ----------------
// grid 8 blocks x 256 threads; block b covers output cols [32b, 32b+32)
__global__ void __launch_bounds__(256) k_h(const float* __restrict__ W0, float invN, int g, int stage) {
    __shared__ float tv[256];
    __shared__ float part[8][33];
    int t = threadIdx.x;
    const float* src = stage ? g_sumax[g] : g_sum[g];
    tv[t] = src[t] * invN;
    __syncthreads();
    int w = t >> 5, l = t & 31;
    int j = blockIdx.x * 32 + l;
    float acc = 0.f;
    const float* col = W0 + (size_t)(w * 32) * 256 + j;
    #pragma unroll 8
    for (int i = 0; i < 32; ++i) acc += tv[w * 32 + i] * col[i * 256];
    part[w][l] = acc;
    __syncthreads();
    if (w == 0) {
        float s = 0.f;
        #pragma unroll
        for (int k = 0; k < 8; ++k) s += part[k][l];
        float* dst = stage ? g_h2[g] : g_h1[g];
        dst[j] = tanhf(s);
    }
}

// ---------------- pass 2: att = sigmoid(x.h1); sum(att*x) ----------------
__global__ void __launch_bounds__(256) k_attsum(const float4* __restrict__ x, int nrows, int g) {
    __shared__ float4 h1s[64];
    __shared__ float bacc[256];
    int t = threadIdx.x;
    bacc[t] = 0.f;
    if (t < 64) h1s[t] = ((const float4*)g_h1[g])[t];
    __syncthreads();
    int lane = t & 31;
    int gw = (blockIdx.x << 3) + (t >> 5);
    int nW = gridDim.x << 3;
    float4 ha = h1s[lane], hb = h1s[lane + 32];
    float4 a0 = make_float4(0.f,0.f,0.f,0.f), a1 = make_float4(0.f,0.f,0.f,0.f);
    for (int r = gw; r < nrows; r += nW) {
        const float4* row = x + (size_t)r * 64;
        float4 v0 = row[lane];
        float4 v1 = row[lane + 32];
        float p = v0.x*ha.x + v0.y*ha.y + v0.z*ha.z + v0.w*ha.w
                + v1.x*hb.x + v1.y*hb.y + v1.z*hb.z + v1.w*hb.w;
        #pragma unroll
        for (int o = 16; o; o >>= 1) p += __shfl_xor_sync(0xffffffffu, p, o);
        float att = sigf_fast(p);
        a0.x += att * v0.x; a0.y += att * v0.y; a0.z += att * v0.z; a0.w += att * v0.w;
        a1.x += att * v1.x; a1.y += att * v1.y; a1.z += att * v1.z; a1.w += att * v1.w;
    }
    int c = lane * 4;
    atomicAdd(&bacc[c + 0], a0.x); atomicAdd(&bacc[c + 1], a0.y);
    atomicAdd(&bacc[c + 2], a0.z); atomicAdd(&bacc[c + 3], a0.w);
    atomicAdd(&bacc[128 + c + 0], a1.x); atomicAdd(&bacc[128 + c + 1], a1.y);
    atomicAdd(&bacc[128 + c + 2], a1.z); atomicAdd(&bacc[128 + c + 3], a1.w);
    __syncthreads();
    atomicAdd(&g_sumax[g][t], bacc[t]);
}

// ---------------- pass 3: out = sum(sig(att*(x.h2))*att*x) ----------------
__global__ void __launch_bounds__(256) k_out(const float4* __restrict__ x, int nrows, int g) {
    __shared__ float4 h1s[64];
    __shared__ float4 h2s[64];
    __shared__ float bacc[256];
    int t = threadIdx.x;
    bacc[t] = 0.f;
    if (t < 64) { h1s[t] = ((const float4*)g_h1[g])[t]; h2s[t] = ((const float4*)g_h2[g])[t]; }
    __syncthreads();
    int lane = t & 31;
    int gw = (blockIdx.x << 3) + (t >> 5);
    int nW = gridDim.x << 3;
    float4 ha = h1s[lane], hb = h1s[lane + 32];
    float4 ga = h2s[lane], gb = h2s[lane + 32];
    float4 a0 = make_float4(0.f,0.f,0.f,0.f), a1 = make_float4(0.f,0.f,0.f,0.f);
    for (int r = gw; r < nrows; r += nW) {
        const float4* row = x + (size_t)r * 64;
        float4 v0 = row[lane];
        float4 v1 = row[lane + 32];
        float p1 = v0.x*ha.x + v0.y*ha.y + v0.z*ha.z + v0.w*ha.w
                 + v1.x*hb.x + v1.y*hb.y + v1.z*hb.z + v1.w*hb.w;
        float p2 = v0.x*ga.x + v0.y*ga.y + v0.z*ga.z + v0.w*ga.w
                 + v1.x*gb.x + v1.y*gb.y + v1.z*gb.z + v1.w*gb.w;
        #pragma unroll
        for (int o = 16; o; o >>= 1) {
            p1 += __shfl_xor_sync(0xffffffffu, p1, o);
            p2 += __shfl_xor_sync(0xffffffffu, p2, o);
        }
        float att  = sigf_fast(p1);
        float att2 = sigf_fast(att * p2);
        float wgt = att * att2;
        a0.x += wgt * v0.x; a0.y += wgt * v0.y; a0.z += wgt * v0.z; a0.w += wgt * v0.w;
        a1.x += wgt * v1.x; a1.y += wgt * v1.y; a1.z += wgt * v1.z; a1.w += wgt * v1.w;
    }
    int c = lane * 4;
    atomicAdd(&bacc[c + 0], a0.x); atomicAdd(&bacc[c + 1], a0.y);
    atomicAdd(&bacc[c + 2], a0.z); atomicAdd(&bacc[c + 3], a0.w);
    atomicAdd(&bacc[128 + c + 0], a1.x); atomicAdd(&bacc[128 + c + 1], a1.y);
    atomicAdd(&bacc[128 + c + 2], a1.z); atomicAdd(&bacc[128 + c + 3], a1.w);
    __syncthreads();
    atomicAdd(&g_outv[g][t], bacc[t]);
}

// ---------------- NTN: w_term (streams W, 16.8MB) + v_term ----------------
// blocks [0,512): f = b>>5, 16-row d-chunk = b&31.   blocks [512,528): v_term for f=b-512
__global__ void __launch_bounds__(256) k_ntn(const float* __restrict__ W, const float* __restrict__ V) {
    __shared__ float g1s[16];
    __shared__ float red[8];
    int b = blockIdx.x, t = threadIdx.x;
    float acc = 0.f;
    int f;
    if (b < 512) {
        f = b >> 5;
        int chunk = b & 31;
        if (t < 16) g1s[t] = g_outv[0][(chunk * 16 + t) & 255];
        __syncthreads();
        float o2 = g_outv[1][t];  // e=t and e=t+256 both map to out2[t]
        const float* base = W + ((size_t)f * 512 + chunk * 16) * 512;
        #pragma unroll
        for (int i = 0; i < 16; ++i) {
            const float* wr = base + (size_t)i * 512;
            acc += g1s[i] * (wr[t] + wr[t + 256]);
        }
        acc *= o2;
    } else {
        f = b - 512;
        const float* vf = V + (size_t)f * 1024;
        acc = g_outv[0][t] * (vf[t] + vf[256 + t])
            + g_outv[1][t] * (vf[512 + t] + vf[768 + t]);
    }
    // block reduce
    #pragma unroll
    for (int o = 16; o; o >>= 1) acc += __shfl_xor_sync(0xffffffffu, acc, o);
    if ((t & 31) == 0) red[t >> 5] = acc;
    __syncthreads();
    if (t < 8) {
        float s = red[t];
        s += __shfl_xor_sync(0xffu, s, 4);
        s += __shfl_xor_sync(0xffu, s, 2);
        s += __shfl_xor_sync(0xffu, s, 1);
        if (t == 0) atomicAdd(&g_wacc[f], s);
    }
}

// ---------------- final: sigmoid(NTN) -> MLP 16->8->4->2->1 ----------------
__global__ void k_final(const float* __restrict__ b, const float* __restrict__ P0,
                        const float* __restrict__ P1, const float* __restrict__ P2,
                        const float* __restrict__ P3, float* __restrict__ out) {
    int t = threadIdx.x;
    __shared__ float s[16];
    if (t < 16) s[t] = 1.f / (1.f + expf(-(g_wacc[t] + b[t])));
    __syncwarp();
    if (t == 0) {
        float y0[8];
        #pragma unroll
        for (int o = 0; o < 8; ++o) {
            float a = 0.f;
            #pragma unroll
            for (int ff = 0; ff < 16; ++ff) a += s[ff] * P0[o * 16 + ff];
            y0[o] = 1.f / (1.f + expf(-a));
        }
        float y1[4];
        #pragma unroll
        for (int o = 0; o < 4; ++o) {
            float a = 0.f;
            #pragma unroll
            for (int ff = 0; ff < 8; ++ff) a += y0[ff] * P1[o * 8 + ff];
            y1[o] = 1.f / (1.f + expf(-a));
        }
        float y2[2];
        #pragma unroll
        for (int o = 0; o < 2; ++o) {
            float a = 0.f;
            #pragma unroll
            for (int ff = 0; ff < 4; ++ff) a += y1[ff] * P2[o * 4 + ff];
            y2[o] = 1.f / (1.f + expf(-a));
        }
        float a = y2[0] * P3[0] + y2[1] * P3[1];
        out[0] = 1.f / (1.f + expf(-a));
    }
}

extern "C" void kernel_launch(void* const* d_in, const int* in_sizes, int n_in,
                              void* d_out, int out_size) {
    const float* x1 = (const float*)d_in[0];
    const float* x2 = (const float*)d_in[1];
    const float* W0 = (const float*)d_in[2];
    const float* V  = (const float*)d_in[3];
    const float* W  = (const float*)d_in[4];
    const float* bb = (const float*)d_in[5];
    const float* P0 = (const float*)d_in[6];
    const float* P1 = (const float*)d_in[7];
    const float* P2 = (const float*)d_in[8];
    const float* P3 = (const float*)d_in[9];
    int N1 = in_sizes[0] / 256;
    int N2 = in_sizes[1] / 256;
    float* out = (float*)d_out;

    k_zero<<<1, 256>>>();

    // graph 1 (x1): 3 streaming passes + 2 tiny matvecs
    k_sum   <<<PGRID, 256>>>((const float4*)x1, N1, 0);
    k_h     <<<8, 256>>>(W0, 1.f / (float)N1, 0, 0);
    k_attsum<<<PGRID, 256>>>((const float4*)x1, N1, 0);
    k_h     <<<8, 256>>>(W0, 1.f / (float)N1, 0, 1);
    k_out   <<<PGRID, 256>>>((const float4*)x1, N1, 0);

    // graph 2 (x2)
    k_sum   <<<PGRID, 256>>>((const float4*)x2, N2, 1);
    k_h     <<<8, 256>>>(W0, 1.f / (float)N2, 1, 0);
    k_attsum<<<PGRID, 256>>>((const float4*)x2, N2, 1);
    k_h     <<<8, 256>>>(W0, 1.f / (float)N2, 1, 1);
    k_out   <<<PGRID, 256>>>((const float4*)x2, N2, 1);

    // NTN bilinear + v_term, then tiny MLP head
    k_ntn  <<<528, 256>>>(W, V);
    k_final<<<1, 32>>>(bb, P0, P1, P2, P3, out);
}